// round 5
// baseline (speedup 1.0000x reference)
#include <cuda_runtime.h>
#include <cuda_bf16.h>
#include <math.h>
#include <float.h>
#include <stdint.h>

// Problem constants
#define B_     16
#define C_     384
#define HEADS_ 6
#define D_     64
#define N_     1024
#define O3C    1152

__device__ float g_qkv[B_ * O3C * N_];
__device__ int g_mask_mode;   // 0 = uint8 bool, 1 = int32, 2 = float32
// Pre-split W: hi/lo bf16 k-pairs, [o][c/2]
__device__ uint32_t g_wh[O3C * (C_ / 2)];
__device__ uint32_t g_wl[O3C * (C_ / 2)];

// ---------------------------------------------------------------------------
__device__ __forceinline__ uint32_t f2tf32(float f) {
    uint32_t r;
    asm("cvt.rna.tf32.f32 %0, %1;" : "=r"(r) : "f"(f));
    return r;
}

// tf32 m16n8k8 row.col mma, f32 acc in-place
__device__ __forceinline__ void mma8(float* c, const uint32_t* a,
                                     uint32_t b0, uint32_t b1) {
    asm volatile(
        "mma.sync.aligned.m16n8k8.row.col.f32.tf32.tf32.f32 "
        "{%0,%1,%2,%3}, {%4,%5,%6,%7}, {%8,%9}, {%0,%1,%2,%3};\n"
        : "+f"(c[0]), "+f"(c[1]), "+f"(c[2]), "+f"(c[3])
        : "r"(a[0]), "r"(a[1]), "r"(a[2]), "r"(a[3]), "r"(b0), "r"(b1));
}

// bf16 m16n8k16 row.col mma, f32 acc in-place
__device__ __forceinline__ void mma16(float* c, const uint32_t* a,
                                      uint32_t b0, uint32_t b1) {
    asm volatile(
        "mma.sync.aligned.m16n8k16.row.col.f32.bf16.bf16.f32 "
        "{%0,%1,%2,%3}, {%4,%5,%6,%7}, {%8,%9}, {%0,%1,%2,%3};\n"
        : "+f"(c[0]), "+f"(c[1]), "+f"(c[2]), "+f"(c[3])
        : "r"(a[0]), "r"(a[1]), "r"(a[2]), "r"(a[3]), "r"(b0), "r"(b1));
}

__device__ __forceinline__ uint32_t pack_bf16(float f0, float f1) {
    __nv_bfloat162 t = __floats2bfloat162_rn(f0, f1);
    return *(uint32_t*)&t;
}

// Fast exp2, FMA-only
__device__ __forceinline__ float fexp2(float y) {
    y = fmaxf(y, -126.0f);
    float z = y + 12582912.0f;
    int   n = __float_as_int(z) - 0x4B400000;
    float f = y - (z - 12582912.0f);
    float p = 1.3333558146e-3f;
    p = fmaf(p, f, 9.6181291076e-3f);
    p = fmaf(p, f, 5.5504108665e-2f);
    p = fmaf(p, f, 2.4022650696e-1f);
    p = fmaf(p, f, 6.9314718056e-1f);
    p = fmaf(p, f, 1.0f);
    return __int_as_float(__float_as_int(p) + (n << 23));
}

// ---------------------------------------------------------------------------
__global__ void detect_mask_kernel(const uint4* __restrict__ m) {
    __shared__ int s_off4, s_gt1;
    if (threadIdx.x == 0) { s_off4 = 0; s_gt1 = 0; }
    __syncthreads();
    int off4 = 0, gt1 = 0;
    for (int i = threadIdx.x; i < 4096; i += blockDim.x) {
        uint4 v = m[i];
        unsigned a = v.x | v.y | v.z | v.w;
        if (a & 0xFFFFFF00u) off4 = 1;
        if (a & 0xFEFEFEFEu) gt1  = 1;
    }
    if (off4) atomicOr(&s_off4, 1);
    if (gt1)  atomicOr(&s_gt1, 1);
    __syncthreads();
    if (threadIdx.x == 0) g_mask_mode = s_gt1 ? 2 : (s_off4 ? 0 : 1);
}

// ---------------------------------------------------------------------------
// Pre-split W into bf16 hi/lo k-pairs (done ONCE, kills 128x redundant cvt)
// ---------------------------------------------------------------------------
__global__ void wsplit_kernel(const float* __restrict__ w) {
    int idx = blockIdx.x * blockDim.x + threadIdx.x;   // pair index
    if (idx >= O3C * (C_ / 2)) return;
    float2 v = *(const float2*)&w[idx * 2];
    __nv_bfloat16 h0 = __float2bfloat16(v.x);
    __nv_bfloat16 h1 = __float2bfloat16(v.y);
    g_wh[idx] = ((uint32_t)*(uint16_t*)&h1 << 16) | *(uint16_t*)&h0;
    g_wl[idx] = pack_bf16(v.x - __bfloat162float(h0),
                          v.y - __bfloat162float(h1));
}

// ---------------------------------------------------------------------------
// QKV GEMM, bf16 hi/lo 3-term, m16n8k16, register-prefetched chunks.
// Tile 128(o) x 128(n), KC=16. 8 warps, warp tile 32(o) x 64(n).
// grid = (8, 9, 16)
// ---------------------------------------------------------------------------
#define WPST 12
#define XPST 136
#define NCHUNK (C_ / 16)

__global__ __launch_bounds__(256, 2) void qkv_gemm_kernel(
    const float* __restrict__ x)
{
    __shared__ uint32_t Whp[128 * WPST], Wlp[128 * WPST];
    __shared__ uint32_t Xhp[8 * XPST],   Xlp[8 * XPST];

    const int b  = blockIdx.z;
    const int o0 = blockIdx.y * 128;
    const int n0 = blockIdx.x * 128;
    const int tid  = threadIdx.x;
    const int wid  = tid >> 5;
    const int lane = tid & 31;
    const int m_base = (wid >> 1) * 32;
    const int n_base = (wid & 1) * 64;
    const int gi = lane >> 2;
    const int ti = lane & 3;

    const float* xb = x + b * C_ * N_;

    // loader indices
    const int wo  = tid >> 1;            // 0..127 (o row)
    const int wk2 = (tid & 1) * 4;       // k-pair offset 0/4
    const int xc2 = tid >> 5;            // 0..7 (c-pair row)
    const int xn  = (tid & 31) * 4;      // n col

    float acc[2][8][4];
    #pragma unroll
    for (int mf = 0; mf < 2; mf++)
        #pragma unroll
        for (int nf = 0; nf < 8; nf++)
            #pragma unroll
            for (int k = 0; k < 4; k++) acc[mf][nf][k] = 0.f;

    // ---- prefetch chunk 0 ----
    const uint32_t* wh_p = &g_wh[(o0 + wo) * (C_ / 2) + wk2];
    const uint32_t* wl_p = &g_wl[(o0 + wo) * (C_ / 2) + wk2];
    const float*    x_p  = &xb[(2 * xc2) * N_ + n0 + xn];
    uint4  whv = *(const uint4*)wh_p;
    uint4  wlv = *(const uint4*)wl_p;
    float4 xr0 = *(const float4*)x_p;
    float4 xr1 = *(const float4*)(x_p + N_);

    for (int ci = 0; ci < NCHUNK; ci++) {
        // ---- store current chunk to smem ----
        *(uint4*)&Whp[wo * WPST + wk2] = whv;
        *(uint4*)&Wlp[wo * WPST + wk2] = wlv;
        {
            float a0[4] = {xr0.x, xr0.y, xr0.z, xr0.w};
            float a1[4] = {xr1.x, xr1.y, xr1.z, xr1.w};
            uint32_t ph[4], pl[4];
            #pragma unroll
            for (int j = 0; j < 4; j++) {
                __nv_bfloat16 h0 = __float2bfloat16(a0[j]);
                __nv_bfloat16 h1 = __float2bfloat16(a1[j]);
                ph[j] = ((uint32_t)*(uint16_t*)&h1 << 16) | *(uint16_t*)&h0;
                pl[j] = pack_bf16(a0[j] - __bfloat162float(h0),
                                  a1[j] - __bfloat162float(h1));
            }
            *(uint4*)&Xhp[xc2 * XPST + xn] = make_uint4(ph[0], ph[1], ph[2], ph[3]);
            *(uint4*)&Xlp[xc2 * XPST + xn] = make_uint4(pl[0], pl[1], pl[2], pl[3]);
        }
        __syncthreads();

        // ---- prefetch next chunk (LDGs overlap with mma below) ----
        if (ci + 1 < NCHUNK) {
            wh_p += 8; wl_p += 8; x_p += 16 * N_;
            whv = *(const uint4*)wh_p;
            wlv = *(const uint4*)wl_p;
            xr0 = *(const float4*)x_p;
            xr1 = *(const float4*)(x_p + N_);
        }

        // ---- compute ----
        uint32_t ah[2][4], al[2][4];
        #pragma unroll
        for (int mf = 0; mf < 2; mf++) {
            int r = m_base + mf * 16 + gi;
            ah[mf][0] = Whp[r * WPST + ti];
            ah[mf][1] = Whp[(r + 8) * WPST + ti];
            ah[mf][2] = Whp[r * WPST + ti + 4];
            ah[mf][3] = Whp[(r + 8) * WPST + ti + 4];
            al[mf][0] = Wlp[r * WPST + ti];
            al[mf][1] = Wlp[(r + 8) * WPST + ti];
            al[mf][2] = Wlp[r * WPST + ti + 4];
            al[mf][3] = Wlp[(r + 8) * WPST + ti + 4];
        }
        #pragma unroll
        for (int nf = 0; nf < 8; nf++) {
            int col = n_base + nf * 8 + gi;
            uint32_t bh0 = Xhp[ti * XPST + col];
            uint32_t bh1 = Xhp[(ti + 4) * XPST + col];
            uint32_t bl0 = Xlp[ti * XPST + col];
            uint32_t bl1 = Xlp[(ti + 4) * XPST + col];
            #pragma unroll
            for (int mf = 0; mf < 2; mf++) {
                mma16(acc[mf][nf], ah[mf], bh0, bh1);
                mma16(acc[mf][nf], ah[mf], bl0, bl1);
                mma16(acc[mf][nf], al[mf], bh0, bh1);
            }
        }
        __syncthreads();
    }

    float* outb = g_qkv + b * O3C * N_;
    #pragma unroll
    for (int mf = 0; mf < 2; mf++) {
        int r = o0 + m_base + mf * 16 + gi;
        #pragma unroll
        for (int nf = 0; nf < 8; nf++) {
            int nc = n0 + n_base + nf * 8 + 2 * ti;
            *(float2*)&outb[r * N_ + nc]       = make_float2(acc[mf][nf][0], acc[mf][nf][1]);
            *(float2*)&outb[(r + 8) * N_ + nc] = make_float2(acc[mf][nf][2], acc[mf][nf][3]);
        }
    }
}

// ---------------------------------------------------------------------------
// Fused flash attention, tf32 mma. Block: 128 q rows, 4 warps, warp M=32
// (2 m-frags -> B-fragments amortized over 2 mma). TK chunk = 64.
// grid = (8, 6, 16).
// ---------------------------------------------------------------------------
#define AST 68
#define KST 72
#define ATTN_SMEM ((128 * AST + 64 * KST + 64 * AST) * 4)

__global__ __launch_bounds__(128, 2) void attn_kernel(
    const unsigned char* __restrict__ mask_raw, float* __restrict__ out)
{
    extern __shared__ uint32_t As[];
    uint32_t* QP = As;                       // [128][AST]  Q then P
    uint32_t* Kn = As + 128 * AST;           // [64][KST]   K: [d][m]
    uint32_t* Vh = Kn + 64 * KST;            // [64][AST]   V: [d][m]
    float*    Od = (float*)Kn;               // [64][132]   output staging

    const int q0 = blockIdx.x * 128;
    const int h  = blockIdx.y;
    const int b  = blockIdx.z;
    const int tid  = threadIdx.x;
    const int wid  = tid >> 5;
    const int lane = tid & 31;
    const int gi = lane >> 2;
    const int ti = lane & 3;
    const int wq = wid * 32;                 // warp covers 32 q rows
    const int mode = g_mask_mode;

    const float sc2 = rsqrtf((float)C_) * 1.4426950408889634f;
    const float NEG = -1e30f;

    const float* qb = g_qkv + (b * O3C + h * D_) * N_;
    const float* kb = qb + C_ * N_;
    const float* vb = qb + 2 * C_ * N_;

    const int* mask_i32   = (const int*)mask_raw;
    const float* mask_f32 = (const float*)mask_raw;
    const int mbase = (b * HEADS_ + h) * N_ * N_;

    // ---- Stage Q tile [128 q x 64 d] transposed (float4 reads) ----
    for (int e = tid; e < 64 * 32; e += 128) {
        int dd = e >> 5, q4 = (e & 31) * 4;
        float4 v = *(const float4*)&qb[dd * N_ + q0 + q4];
        QP[(q4 + 0) * AST + dd] = f2tf32(v.x);
        QP[(q4 + 1) * AST + dd] = f2tf32(v.y);
        QP[(q4 + 2) * AST + dd] = f2tf32(v.z);
        QP[(q4 + 3) * AST + dd] = f2tf32(v.w);
    }
    __syncthreads();

    // ---- Cache Q A-fragments (2 m-frags) in registers ----
    uint32_t qa[2][8][4];
    #pragma unroll
    for (int mf = 0; mf < 2; mf++) {
        int r = wq + mf * 16 + gi;
        #pragma unroll
        for (int ks = 0; ks < 8; ks++) {
            int c = ks * 8 + ti;
            qa[mf][ks][0] = QP[r * AST + c];
            qa[mf][ks][1] = QP[(r + 8) * AST + c];
            qa[mf][ks][2] = QP[r * AST + c + 4];
            qa[mf][ks][3] = QP[(r + 8) * AST + c + 4];
        }
    }
    __syncthreads();

    float oa[2][8][4];
    float mm[2][2], ll[2][2];
    #pragma unroll
    for (int mf = 0; mf < 2; mf++) {
        mm[mf][0] = NEG; mm[mf][1] = NEG;
        ll[mf][0] = 0.f; ll[mf][1] = 0.f;
        #pragma unroll
        for (int nf = 0; nf < 8; nf++)
            #pragma unroll
            for (int k = 0; k < 4; k++) oa[mf][nf][k] = 0.f;
    }

    for (int k0 = 0; k0 < N_; k0 += 64) {
        // ---- Fill K [d][m] and V [d][m], coalesced float4 ----
        for (int e = tid; e < 1024; e += 128) {
            int dd = e >> 4, m4 = (e & 15) * 4;
            float4 kv = *(const float4*)&kb[dd * N_ + k0 + m4];
            *(uint4*)&Kn[dd * KST + m4] =
                make_uint4(f2tf32(kv.x), f2tf32(kv.y), f2tf32(kv.z), f2tf32(kv.w));
            float4 vv = *(const float4*)&vb[dd * N_ + k0 + m4];
            *(uint4*)&Vh[dd * AST + m4] =
                make_uint4(f2tf32(vv.x), f2tf32(vv.y), f2tf32(vv.z), f2tf32(vv.w));
        }
        __syncthreads();

        // ---- S = Q K^T : warp computes [32 x 64], B shared across m-frags ----
        float sa[2][8][4];
        #pragma unroll
        for (int mf = 0; mf < 2; mf++)
            #pragma unroll
            for (int nf = 0; nf < 8; nf++)
                #pragma unroll
                for (int k = 0; k < 4; k++) sa[mf][nf][k] = 0.f;
        #pragma unroll
        for (int ks = 0; ks < 8; ks++) {
            #pragma unroll
            for (int nf = 0; nf < 8; nf++) {
                uint32_t b0 = Kn[(ks * 8 + ti) * KST + nf * 8 + gi];
                uint32_t b1 = Kn[(ks * 8 + ti + 4) * KST + nf * 8 + gi];
                mma8(sa[0][nf], qa[0][ks], b0, b1);
                mma8(sa[1][nf], qa[1][ks], b0, b1);
            }
        }

        // ---- scale + mask + online softmax + P write, per m-frag ----
        #pragma unroll
        for (int mf = 0; mf < 2; mf++) {
            const int r1g = q0 + wq + mf * 16 + gi;
            #pragma unroll
            for (int nf = 0; nf < 8; nf++) {
                int cb = k0 + nf * 8 + 2 * ti;
                int i1 = mbase + r1g * N_ + cb;
                int i2 = i1 + 8 * N_;
                bool k00, k01, k10, k11;
                if (mode == 0) {
                    uchar2 a = *(const uchar2*)&mask_raw[i1];
                    uchar2 c = *(const uchar2*)&mask_raw[i2];
                    k00 = a.x; k01 = a.y; k10 = c.x; k11 = c.y;
                } else if (mode == 1) {
                    int2 a = *(const int2*)&mask_i32[i1];
                    int2 c = *(const int2*)&mask_i32[i2];
                    k00 = a.x; k01 = a.y; k10 = c.x; k11 = c.y;
                } else {
                    float2 a = *(const float2*)&mask_f32[i1];
                    float2 c = *(const float2*)&mask_f32[i2];
                    k00 = a.x != 0.f; k01 = a.y != 0.f;
                    k10 = c.x != 0.f; k11 = c.y != 0.f;
                }
                sa[mf][nf][0] = k00 ? NEG : sa[mf][nf][0] * sc2;
                sa[mf][nf][1] = k01 ? NEG : sa[mf][nf][1] * sc2;
                sa[mf][nf][2] = k10 ? NEG : sa[mf][nf][2] * sc2;
                sa[mf][nf][3] = k11 ? NEG : sa[mf][nf][3] * sc2;
            }

            float mx1 = NEG, mx2 = NEG;
            #pragma unroll
            for (int nf = 0; nf < 8; nf++) {
                mx1 = fmaxf(mx1, fmaxf(sa[mf][nf][0], sa[mf][nf][1]));
                mx2 = fmaxf(mx2, fmaxf(sa[mf][nf][2], sa[mf][nf][3]));
            }
            mx1 = fmaxf(mx1, __shfl_xor_sync(0xffffffffu, mx1, 1));
            mx1 = fmaxf(mx1, __shfl_xor_sync(0xffffffffu, mx1, 2));
            mx2 = fmaxf(mx2, __shfl_xor_sync(0xffffffffu, mx2, 1));
            mx2 = fmaxf(mx2, __shfl_xor_sync(0xffffffffu, mx2, 2));
            float mn1 = fmaxf(mm[mf][0], mx1), mn2 = fmaxf(mm[mf][1], mx2);
            float corr1 = fexp2(mm[mf][0] - mn1), corr2 = fexp2(mm[mf][1] - mn2);

            float ls1 = 0.f, ls2 = 0.f;
            const int rl = wq + mf * 16 + gi;
            #pragma unroll
            for (int nf = 0; nf < 8; nf++) {
                float p00 = fexp2(sa[mf][nf][0] - mn1);
                float p01 = fexp2(sa[mf][nf][1] - mn1);
                float p10 = fexp2(sa[mf][nf][2] - mn2);
                float p11 = fexp2(sa[mf][nf][3] - mn2);
                ls1 += p00 + p01;
                ls2 += p10 + p11;
                int col = nf * 8 + 2 * ti;
                QP[rl * AST + col]           = f2tf32(p00);
                QP[rl * AST + col + 1]       = f2tf32(p01);
                QP[(rl + 8) * AST + col]     = f2tf32(p10);
                QP[(rl + 8) * AST + col + 1] = f2tf32(p11);
            }
            ls1 += __shfl_xor_sync(0xffffffffu, ls1, 1);
            ls1 += __shfl_xor_sync(0xffffffffu, ls1, 2);
            ls2 += __shfl_xor_sync(0xffffffffu, ls2, 1);
            ls2 += __shfl_xor_sync(0xffffffffu, ls2, 2);
            ll[mf][0] = ll[mf][0] * corr1 + ls1;
            ll[mf][1] = ll[mf][1] * corr2 + ls2;
            mm[mf][0] = mn1; mm[mf][1] = mn2;
            #pragma unroll
            for (int nf = 0; nf < 8; nf++) {
                oa[mf][nf][0] *= corr1; oa[mf][nf][1] *= corr1;
                oa[mf][nf][2] *= corr2; oa[mf][nf][3] *= corr2;
            }
        }
        __syncwarp();   // P warp-local

        // ---- O += P V : B shared across m-frags ----
        #pragma unroll
        for (int kf = 0; kf < 8; kf++) {
            uint32_t pa[2][4];
            #pragma unroll
            for (int mf = 0; mf < 2; mf++) {
                int r = wq + mf * 16 + gi, c = kf * 8 + ti;
                pa[mf][0] = QP[r * AST + c];
                pa[mf][1] = QP[(r + 8) * AST + c];
                pa[mf][2] = QP[r * AST + c + 4];
                pa[mf][3] = QP[(r + 8) * AST + c + 4];
            }
            #pragma unroll
            for (int nf = 0; nf < 8; nf++) {
                uint32_t b0 = Vh[(nf * 8 + gi) * AST + kf * 8 + ti];
                uint32_t b1 = Vh[(nf * 8 + gi) * AST + kf * 8 + ti + 4];
                mma8(oa[0][nf], pa[0], b0, b1);
                mma8(oa[1][nf], pa[1], b0, b1);
            }
        }
        __syncthreads();
    }

    // ---- normalize + stage to smem [d][q] for coalesced output ----
    #pragma unroll
    for (int mf = 0; mf < 2; mf++) {
        float il1 = 1.0f / ll[mf][0], il2 = 1.0f / ll[mf][1];
        int qi = wq + mf * 16 + gi;
        #pragma unroll
        for (int nf = 0; nf < 8; nf++) {
            int d0 = nf * 8 + 2 * ti;
            Od[d0 * 132 + qi]           = oa[mf][nf][0] * il1;
            Od[(d0 + 1) * 132 + qi]     = oa[mf][nf][1] * il1;
            Od[d0 * 132 + qi + 8]       = oa[mf][nf][2] * il2;
            Od[(d0 + 1) * 132 + qi + 8] = oa[mf][nf][3] * il2;
        }
    }
    __syncthreads();

    float* ob = out + (b * C_ + h * D_) * N_;
    for (int e = tid; e < 64 * 32; e += 128) {
        int dd = e >> 5, q4 = (e & 31) * 4;
        *(float4*)&ob[dd * N_ + q0 + q4] = *(const float4*)&Od[dd * 132 + q4];
    }
}

// ---------------------------------------------------------------------------
extern "C" void kernel_launch(void* const* d_in, const int* in_sizes, int n_in,
                              void* d_out, int out_size)
{
    const float* x         = (const float*)d_in[0];
    const float* w_qkv     = (const float*)d_in[1];
    const unsigned char* m = (const unsigned char*)d_in[2];
    float* out             = (float*)d_out;

    cudaFuncSetAttribute(attn_kernel,
                         cudaFuncAttributeMaxDynamicSharedMemorySize, ATTN_SMEM);

    detect_mask_kernel<<<1, 1024>>>((const uint4*)m);
    wsplit_kernel<<<(O3C * (C_ / 2) + 255) / 256, 256>>>(w_qkv);

    dim3 gemm_grid(N_ / 128, O3C / 128, B_);   // (8, 9, 16)
    qkv_gemm_kernel<<<gemm_grid, 256>>>(x);

    dim3 attn_grid(N_ / 128, HEADS_, B_);      // (8, 6, 16)
    attn_kernel<<<attn_grid, 128, ATTN_SMEM>>>(m, out);
}

// round 6
// speedup vs baseline: 1.2319x; 1.2319x over previous
#include <cuda_runtime.h>
#include <cuda_bf16.h>
#include <math.h>
#include <float.h>
#include <stdint.h>

// Problem constants
#define B_     16
#define C_     384
#define HEADS_ 6
#define D_     64
#define N_     1024
#define O3C    1152

__device__ float g_qkv[B_ * O3C * N_];
__device__ int g_mask_mode;   // 0 = uint8 bool, 1 = int32, 2 = float32
// Pre-split W: hi/lo bf16 k-pairs, [o][c/2]
__device__ uint32_t g_wh[O3C * (C_ / 2)];
__device__ uint32_t g_wl[O3C * (C_ / 2)];

// ---------------------------------------------------------------------------
__device__ __forceinline__ uint32_t f2tf32(float f) {
    uint32_t r;
    asm("cvt.rna.tf32.f32 %0, %1;" : "=r"(r) : "f"(f));
    return r;
}

// tf32 m16n8k8 row.col mma, f32 acc in-place
__device__ __forceinline__ void mma8(float* c, const uint32_t* a,
                                     uint32_t b0, uint32_t b1) {
    asm volatile(
        "mma.sync.aligned.m16n8k8.row.col.f32.tf32.tf32.f32 "
        "{%0,%1,%2,%3}, {%4,%5,%6,%7}, {%8,%9}, {%0,%1,%2,%3};\n"
        : "+f"(c[0]), "+f"(c[1]), "+f"(c[2]), "+f"(c[3])
        : "r"(a[0]), "r"(a[1]), "r"(a[2]), "r"(a[3]), "r"(b0), "r"(b1));
}

// bf16 m16n8k16 row.col mma, f32 acc in-place
__device__ __forceinline__ void mma16(float* c, const uint32_t* a,
                                      uint32_t b0, uint32_t b1) {
    asm volatile(
        "mma.sync.aligned.m16n8k16.row.col.f32.bf16.bf16.f32 "
        "{%0,%1,%2,%3}, {%4,%5,%6,%7}, {%8,%9}, {%0,%1,%2,%3};\n"
        : "+f"(c[0]), "+f"(c[1]), "+f"(c[2]), "+f"(c[3])
        : "r"(a[0]), "r"(a[1]), "r"(a[2]), "r"(a[3]), "r"(b0), "r"(b1));
}

__device__ __forceinline__ uint32_t pack_bf16(float f0, float f1) {
    __nv_bfloat162 t = __floats2bfloat162_rn(f0, f1);
    return *(uint32_t*)&t;
}

// Fast exp2, FMA-only
__device__ __forceinline__ float fexp2(float y) {
    y = fmaxf(y, -126.0f);
    float z = y + 12582912.0f;
    int   n = __float_as_int(z) - 0x4B400000;
    float f = y - (z - 12582912.0f);
    float p = 1.3333558146e-3f;
    p = fmaf(p, f, 9.6181291076e-3f);
    p = fmaf(p, f, 5.5504108665e-2f);
    p = fmaf(p, f, 2.4022650696e-1f);
    p = fmaf(p, f, 6.9314718056e-1f);
    p = fmaf(p, f, 1.0f);
    return __int_as_float(__float_as_int(p) + (n << 23));
}

// ---------------------------------------------------------------------------
__global__ void detect_mask_kernel(const uint4* __restrict__ m) {
    __shared__ int s_off4, s_gt1;
    if (threadIdx.x == 0) { s_off4 = 0; s_gt1 = 0; }
    __syncthreads();
    int off4 = 0, gt1 = 0;
    for (int i = threadIdx.x; i < 4096; i += blockDim.x) {
        uint4 v = m[i];
        unsigned a = v.x | v.y | v.z | v.w;
        if (a & 0xFFFFFF00u) off4 = 1;
        if (a & 0xFEFEFEFEu) gt1  = 1;
    }
    if (off4) atomicOr(&s_off4, 1);
    if (gt1)  atomicOr(&s_gt1, 1);
    __syncthreads();
    if (threadIdx.x == 0) g_mask_mode = s_gt1 ? 2 : (s_off4 ? 0 : 1);
}

// ---------------------------------------------------------------------------
// Pre-split W into bf16 hi/lo k-pairs (done ONCE)
// ---------------------------------------------------------------------------
__global__ void wsplit_kernel(const float* __restrict__ w) {
    int idx = blockIdx.x * blockDim.x + threadIdx.x;   // pair index
    if (idx >= O3C * (C_ / 2)) return;
    float2 v = *(const float2*)&w[idx * 2];
    __nv_bfloat16 h0 = __float2bfloat16(v.x);
    __nv_bfloat16 h1 = __float2bfloat16(v.y);
    g_wh[idx] = ((uint32_t)*(uint16_t*)&h1 << 16) | *(uint16_t*)&h0;
    g_wl[idx] = pack_bf16(v.x - __bfloat162float(h0),
                          v.y - __bfloat162float(h1));
}

// ---------------------------------------------------------------------------
// QKV GEMM, bf16 hi/lo 3-term, m16n8k16, register-prefetched chunks.
// Tile 128(o) x 128(n), KC=16. 8 warps, warp tile 32(o) x 64(n).
// grid = (8, 9, 16)
// ---------------------------------------------------------------------------
#define WPST 12
#define XPST 136
#define NCHUNK (C_ / 16)

__global__ __launch_bounds__(256, 2) void qkv_gemm_kernel(
    const float* __restrict__ x)
{
    __shared__ uint32_t Whp[128 * WPST], Wlp[128 * WPST];
    __shared__ uint32_t Xhp[8 * XPST],   Xlp[8 * XPST];

    const int b  = blockIdx.z;
    const int o0 = blockIdx.y * 128;
    const int n0 = blockIdx.x * 128;
    const int tid  = threadIdx.x;
    const int wid  = tid >> 5;
    const int lane = tid & 31;
    const int m_base = (wid >> 1) * 32;
    const int n_base = (wid & 1) * 64;
    const int gi = lane >> 2;
    const int ti = lane & 3;

    const float* xb = x + b * C_ * N_;

    const int wo  = tid >> 1;            // 0..127 (o row)
    const int wk2 = (tid & 1) * 4;       // k-pair offset 0/4
    const int xc2 = tid >> 5;            // 0..7 (c-pair row)
    const int xn  = (tid & 31) * 4;      // n col

    float acc[2][8][4];
    #pragma unroll
    for (int mf = 0; mf < 2; mf++)
        #pragma unroll
        for (int nf = 0; nf < 8; nf++)
            #pragma unroll
            for (int k = 0; k < 4; k++) acc[mf][nf][k] = 0.f;

    // ---- prefetch chunk 0 ----
    const uint32_t* wh_p = &g_wh[(o0 + wo) * (C_ / 2) + wk2];
    const uint32_t* wl_p = &g_wl[(o0 + wo) * (C_ / 2) + wk2];
    const float*    x_p  = &xb[(2 * xc2) * N_ + n0 + xn];
    uint4  whv = *(const uint4*)wh_p;
    uint4  wlv = *(const uint4*)wl_p;
    float4 xr0 = *(const float4*)x_p;
    float4 xr1 = *(const float4*)(x_p + N_);

    for (int ci = 0; ci < NCHUNK; ci++) {
        *(uint4*)&Whp[wo * WPST + wk2] = whv;
        *(uint4*)&Wlp[wo * WPST + wk2] = wlv;
        {
            float a0[4] = {xr0.x, xr0.y, xr0.z, xr0.w};
            float a1[4] = {xr1.x, xr1.y, xr1.z, xr1.w};
            uint32_t ph[4], pl[4];
            #pragma unroll
            for (int j = 0; j < 4; j++) {
                __nv_bfloat16 h0 = __float2bfloat16(a0[j]);
                __nv_bfloat16 h1 = __float2bfloat16(a1[j]);
                ph[j] = ((uint32_t)*(uint16_t*)&h1 << 16) | *(uint16_t*)&h0;
                pl[j] = pack_bf16(a0[j] - __bfloat162float(h0),
                                  a1[j] - __bfloat162float(h1));
            }
            *(uint4*)&Xhp[xc2 * XPST + xn] = make_uint4(ph[0], ph[1], ph[2], ph[3]);
            *(uint4*)&Xlp[xc2 * XPST + xn] = make_uint4(pl[0], pl[1], pl[2], pl[3]);
        }
        __syncthreads();

        if (ci + 1 < NCHUNK) {
            wh_p += 8; wl_p += 8; x_p += 16 * N_;
            whv = *(const uint4*)wh_p;
            wlv = *(const uint4*)wl_p;
            xr0 = *(const float4*)x_p;
            xr1 = *(const float4*)(x_p + N_);
        }

        uint32_t ah[2][4], al[2][4];
        #pragma unroll
        for (int mf = 0; mf < 2; mf++) {
            int r = m_base + mf * 16 + gi;
            ah[mf][0] = Whp[r * WPST + ti];
            ah[mf][1] = Whp[(r + 8) * WPST + ti];
            ah[mf][2] = Whp[r * WPST + ti + 4];
            ah[mf][3] = Whp[(r + 8) * WPST + ti + 4];
            al[mf][0] = Wlp[r * WPST + ti];
            al[mf][1] = Wlp[(r + 8) * WPST + ti];
            al[mf][2] = Wlp[r * WPST + ti + 4];
            al[mf][3] = Wlp[(r + 8) * WPST + ti + 4];
        }
        #pragma unroll
        for (int nf = 0; nf < 8; nf++) {
            int col = n_base + nf * 8 + gi;
            uint32_t bh0 = Xhp[ti * XPST + col];
            uint32_t bh1 = Xhp[(ti + 4) * XPST + col];
            uint32_t bl0 = Xlp[ti * XPST + col];
            uint32_t bl1 = Xlp[(ti + 4) * XPST + col];
            #pragma unroll
            for (int mf = 0; mf < 2; mf++) {
                mma16(acc[mf][nf], ah[mf], bh0, bh1);
                mma16(acc[mf][nf], ah[mf], bl0, bl1);
                mma16(acc[mf][nf], al[mf], bh0, bh1);
            }
        }
        __syncthreads();
    }

    float* outb = g_qkv + b * O3C * N_;
    #pragma unroll
    for (int mf = 0; mf < 2; mf++) {
        int r = o0 + m_base + mf * 16 + gi;
        #pragma unroll
        for (int nf = 0; nf < 8; nf++) {
            int nc = n0 + n_base + nf * 8 + 2 * ti;
            *(float2*)&outb[r * N_ + nc]       = make_float2(acc[mf][nf][0], acc[mf][nf][1]);
            *(float2*)&outb[(r + 8) * N_ + nc] = make_float2(acc[mf][nf][2], acc[mf][nf][3]);
        }
    }
}

// ---------------------------------------------------------------------------
// Fused flash attention, tf32 mma. Block: 128 q rows, 8 warps (16 q each).
// TK chunk = 64. grid = (8, 6, 16).  [R4 shape: 2 CTA/SM, 16 warps/SM]
// ---------------------------------------------------------------------------
#define AST 68
#define KST 72
#define ATTN_SMEM ((128 * AST + 64 * KST + 64 * AST) * 4)

__global__ __launch_bounds__(256, 2) void attn_kernel(
    const unsigned char* __restrict__ mask_raw, float* __restrict__ out)
{
    extern __shared__ uint32_t As[];
    uint32_t* QP = As;                       // [128][AST]  Q then P
    uint32_t* Kn = As + 128 * AST;           // [64][KST]   K: [d][m]
    uint32_t* Vh = Kn + 64 * KST;            // [64][AST]   V: [d][m]
    float*    Od = (float*)Kn;               // [64][132]   output staging

    const int q0 = blockIdx.x * 128;
    const int h  = blockIdx.y;
    const int b  = blockIdx.z;
    const int tid  = threadIdx.x;
    const int wid  = tid >> 5;
    const int lane = tid & 31;
    const int gi = lane >> 2;
    const int ti = lane & 3;
    const int wq = wid * 16;
    const int mode = g_mask_mode;

    const float sc2 = rsqrtf((float)C_) * 1.4426950408889634f;
    const float NEG = -1e30f;

    const float* qb = g_qkv + (b * O3C + h * D_) * N_;
    const float* kb = qb + C_ * N_;
    const float* vb = qb + 2 * C_ * N_;

    const int* mask_i32   = (const int*)mask_raw;
    const float* mask_f32 = (const float*)mask_raw;
    const int mbase = (b * HEADS_ + h) * N_ * N_;

    // ---- Stage Q tile [128 q x 64 d] transposed (float4 reads) ----
    for (int e = tid; e < 64 * 32; e += 256) {
        int dd = e >> 5, q4 = (e & 31) * 4;
        float4 v = *(const float4*)&qb[dd * N_ + q0 + q4];
        QP[(q4 + 0) * AST + dd] = f2tf32(v.x);
        QP[(q4 + 1) * AST + dd] = f2tf32(v.y);
        QP[(q4 + 2) * AST + dd] = f2tf32(v.z);
        QP[(q4 + 3) * AST + dd] = f2tf32(v.w);
    }
    __syncthreads();

    // ---- Cache Q A-fragments in registers ----
    uint32_t qa[8][4];
    #pragma unroll
    for (int ks = 0; ks < 8; ks++) {
        int r = wq + gi, c = ks * 8 + ti;
        qa[ks][0] = QP[r * AST + c];
        qa[ks][1] = QP[(r + 8) * AST + c];
        qa[ks][2] = QP[r * AST + c + 4];
        qa[ks][3] = QP[(r + 8) * AST + c + 4];
    }
    __syncthreads();

    float oa[8][4];
    #pragma unroll
    for (int nf = 0; nf < 8; nf++)
        #pragma unroll
        for (int k = 0; k < 4; k++) oa[nf][k] = 0.f;
    float m1 = NEG, m2 = NEG, l1 = 0.f, l2 = 0.f;

    const int r1g = q0 + wq + gi;

    for (int k0 = 0; k0 < N_; k0 += 64) {
        // ---- Fill K [d][m] and V [d][m], both coalesced float4 ----
        for (int e = tid; e < 1024; e += 256) {
            int dd = e >> 4, m4 = (e & 15) * 4;
            float4 kv = *(const float4*)&kb[dd * N_ + k0 + m4];
            *(uint4*)&Kn[dd * KST + m4] =
                make_uint4(f2tf32(kv.x), f2tf32(kv.y), f2tf32(kv.z), f2tf32(kv.w));
            float4 vv = *(const float4*)&vb[dd * N_ + k0 + m4];
            *(uint4*)&Vh[dd * AST + m4] =
                make_uint4(f2tf32(vv.x), f2tf32(vv.y), f2tf32(vv.z), f2tf32(vv.w));
        }
        __syncthreads();

        // ---- S = Q K^T : warp computes [16 x 64] ----
        float sa[8][4];
        #pragma unroll
        for (int nf = 0; nf < 8; nf++)
            #pragma unroll
            for (int k = 0; k < 4; k++) sa[nf][k] = 0.f;
        #pragma unroll
        for (int ks = 0; ks < 8; ks++) {
            #pragma unroll
            for (int nf = 0; nf < 8; nf++) {
                uint32_t b0 = Kn[(ks * 8 + ti) * KST + nf * 8 + gi];
                uint32_t b1 = Kn[(ks * 8 + ti + 4) * KST + nf * 8 + gi];
                mma8(sa[nf], qa[ks], b0, b1);
            }
        }

        // ---- scale + mask ----
        #pragma unroll
        for (int nf = 0; nf < 8; nf++) {
            int cb = k0 + nf * 8 + 2 * ti;
            int i1 = mbase + r1g * N_ + cb;
            int i2 = i1 + 8 * N_;
            bool k00, k01, k10, k11;
            if (mode == 0) {
                uchar2 a = *(const uchar2*)&mask_raw[i1];
                uchar2 c = *(const uchar2*)&mask_raw[i2];
                k00 = a.x; k01 = a.y; k10 = c.x; k11 = c.y;
            } else if (mode == 1) {
                int2 a = *(const int2*)&mask_i32[i1];
                int2 c = *(const int2*)&mask_i32[i2];
                k00 = a.x; k01 = a.y; k10 = c.x; k11 = c.y;
            } else {
                float2 a = *(const float2*)&mask_f32[i1];
                float2 c = *(const float2*)&mask_f32[i2];
                k00 = a.x != 0.f; k01 = a.y != 0.f; k10 = c.x != 0.f; k11 = c.y != 0.f;
            }
            sa[nf][0] = k00 ? NEG : sa[nf][0] * sc2;
            sa[nf][1] = k01 ? NEG : sa[nf][1] * sc2;
            sa[nf][2] = k10 ? NEG : sa[nf][2] * sc2;
            sa[nf][3] = k11 ? NEG : sa[nf][3] * sc2;
        }

        // ---- online softmax ----
        float mx1 = NEG, mx2 = NEG;
        #pragma unroll
        for (int nf = 0; nf < 8; nf++) {
            mx1 = fmaxf(mx1, fmaxf(sa[nf][0], sa[nf][1]));
            mx2 = fmaxf(mx2, fmaxf(sa[nf][2], sa[nf][3]));
        }
        mx1 = fmaxf(mx1, __shfl_xor_sync(0xffffffffu, mx1, 1));
        mx1 = fmaxf(mx1, __shfl_xor_sync(0xffffffffu, mx1, 2));
        mx2 = fmaxf(mx2, __shfl_xor_sync(0xffffffffu, mx2, 1));
        mx2 = fmaxf(mx2, __shfl_xor_sync(0xffffffffu, mx2, 2));
        float mn1 = fmaxf(m1, mx1), mn2 = fmaxf(m2, mx2);
        float corr1 = fexp2(m1 - mn1), corr2 = fexp2(m2 - mn2);

        float ls1 = 0.f, ls2 = 0.f;
        #pragma unroll
        for (int nf = 0; nf < 8; nf++) {
            float p00 = fexp2(sa[nf][0] - mn1);
            float p01 = fexp2(sa[nf][1] - mn1);
            float p10 = fexp2(sa[nf][2] - mn2);
            float p11 = fexp2(sa[nf][3] - mn2);
            ls1 += p00 + p01;
            ls2 += p10 + p11;
            int col = nf * 8 + 2 * ti;
            QP[(wq + gi) * AST + col]         = f2tf32(p00);
            QP[(wq + gi) * AST + col + 1]     = f2tf32(p01);
            QP[(wq + gi + 8) * AST + col]     = f2tf32(p10);
            QP[(wq + gi + 8) * AST + col + 1] = f2tf32(p11);
        }
        ls1 += __shfl_xor_sync(0xffffffffu, ls1, 1);
        ls1 += __shfl_xor_sync(0xffffffffu, ls1, 2);
        ls2 += __shfl_xor_sync(0xffffffffu, ls2, 1);
        ls2 += __shfl_xor_sync(0xffffffffu, ls2, 2);
        l1 = l1 * corr1 + ls1;
        l2 = l2 * corr2 + ls2;
        m1 = mn1; m2 = mn2;
        #pragma unroll
        for (int nf = 0; nf < 8; nf++) {
            oa[nf][0] *= corr1; oa[nf][1] *= corr1;
            oa[nf][2] *= corr2; oa[nf][3] *= corr2;
        }
        __syncwarp();

        // ---- O += P V ----
        #pragma unroll
        for (int kf = 0; kf < 8; kf++) {
            uint32_t pa[4];
            int r = wq + gi, c = kf * 8 + ti;
            pa[0] = QP[r * AST + c];
            pa[1] = QP[(r + 8) * AST + c];
            pa[2] = QP[r * AST + c + 4];
            pa[3] = QP[(r + 8) * AST + c + 4];
            #pragma unroll
            for (int nf = 0; nf < 8; nf++) {
                uint32_t b0 = Vh[(nf * 8 + gi) * AST + kf * 8 + ti];
                uint32_t b1 = Vh[(nf * 8 + gi) * AST + kf * 8 + ti + 4];
                mma8(oa[nf], pa, b0, b1);
            }
        }
        __syncthreads();
    }

    // ---- normalize + stage to smem [d][q] for coalesced output ----
    float il1 = 1.0f / l1, il2 = 1.0f / l2;
    #pragma unroll
    for (int nf = 0; nf < 8; nf++) {
        int d0 = nf * 8 + 2 * ti;
        Od[d0 * 132 + wq + gi]           = oa[nf][0] * il1;
        Od[(d0 + 1) * 132 + wq + gi]     = oa[nf][1] * il1;
        Od[d0 * 132 + wq + gi + 8]       = oa[nf][2] * il2;
        Od[(d0 + 1) * 132 + wq + gi + 8] = oa[nf][3] * il2;
    }
    __syncthreads();

    float* ob = out + (b * C_ + h * D_) * N_;
    for (int e = tid; e < 64 * 32; e += 256) {
        int dd = e >> 5, q4 = (e & 31) * 4;
        *(float4*)&ob[dd * N_ + q0 + q4] = *(const float4*)&Od[dd * 132 + q4];
    }
}

// ---------------------------------------------------------------------------
extern "C" void kernel_launch(void* const* d_in, const int* in_sizes, int n_in,
                              void* d_out, int out_size)
{
    const float* x         = (const float*)d_in[0];
    const float* w_qkv     = (const float*)d_in[1];
    const unsigned char* m = (const unsigned char*)d_in[2];
    float* out             = (float*)d_out;

    cudaFuncSetAttribute(attn_kernel,
                         cudaFuncAttributeMaxDynamicSharedMemorySize, ATTN_SMEM);

    detect_mask_kernel<<<1, 1024>>>((const uint4*)m);
    wsplit_kernel<<<(O3C * (C_ / 2) + 255) / 256, 256>>>(w_qkv);

    dim3 gemm_grid(N_ / 128, O3C / 128, B_);   // (8, 9, 16)
    qkv_gemm_kernel<<<gemm_grid, 256>>>(x);

    dim3 attn_grid(N_ / 128, HEADS_, B_);      // (8, 6, 16)
    attn_kernel<<<attn_grid, 256, ATTN_SMEM>>>(m, out);
}

// round 7
// speedup vs baseline: 1.3799x; 1.1201x over previous
#include <cuda_runtime.h>
#include <cuda_bf16.h>
#include <math.h>
#include <float.h>
#include <stdint.h>

// Problem constants
#define B_     16
#define C_     384
#define HEADS_ 6
#define D_     64
#define N_     1024
#define O3C    1152

__device__ float g_qkv[B_ * O3C * N_];   // tf32-rounded values (GEMM epilogue)
__device__ int g_mask_mode;              // 0 = uint8 bool, 1 = int32, 2 = float32
#define MWORDS (B_ * HEADS_ * N_ * (N_ / 32))
__device__ uint32_t g_mbits[MWORDS];     // bit-packed drop mask
// Pre-split W: hi/lo bf16 k-pairs, [o][c/2]
__device__ uint32_t g_wh[O3C * (C_ / 2)];
__device__ uint32_t g_wl[O3C * (C_ / 2)];

// ---------------------------------------------------------------------------
__device__ __forceinline__ uint32_t f2tf32(float f) {
    uint32_t r;
    asm("cvt.rna.tf32.f32 %0, %1;" : "=r"(r) : "f"(f));
    return r;
}

// tf32 m16n8k8 row.col mma, f32 acc in-place
__device__ __forceinline__ void mma8(float* c, const uint32_t* a,
                                     uint32_t b0, uint32_t b1) {
    asm volatile(
        "mma.sync.aligned.m16n8k8.row.col.f32.tf32.tf32.f32 "
        "{%0,%1,%2,%3}, {%4,%5,%6,%7}, {%8,%9}, {%0,%1,%2,%3};\n"
        : "+f"(c[0]), "+f"(c[1]), "+f"(c[2]), "+f"(c[3])
        : "r"(a[0]), "r"(a[1]), "r"(a[2]), "r"(a[3]), "r"(b0), "r"(b1));
}

// bf16 m16n8k16 row.col mma, f32 acc in-place
__device__ __forceinline__ void mma16(float* c, const uint32_t* a,
                                      uint32_t b0, uint32_t b1) {
    asm volatile(
        "mma.sync.aligned.m16n8k16.row.col.f32.bf16.bf16.f32 "
        "{%0,%1,%2,%3}, {%4,%5,%6,%7}, {%8,%9}, {%0,%1,%2,%3};\n"
        : "+f"(c[0]), "+f"(c[1]), "+f"(c[2]), "+f"(c[3])
        : "r"(a[0]), "r"(a[1]), "r"(a[2]), "r"(a[3]), "r"(b0), "r"(b1));
}

__device__ __forceinline__ uint32_t pack_bf16(float f0, float f1) {
    __nv_bfloat162 t = __floats2bfloat162_rn(f0, f1);
    return *(uint32_t*)&t;
}

// 16B async copy gmem -> smem (L2 path)
__device__ __forceinline__ void cpa16(void* smem, const void* g) {
    uint32_t s = (uint32_t)__cvta_generic_to_shared(smem);
    asm volatile("cp.async.cg.shared.global [%0], [%1], 16;" :: "r"(s), "l"(g));
}

// Fast exp2, FMA-only
__device__ __forceinline__ float fexp2(float y) {
    y = fmaxf(y, -126.0f);
    float z = y + 12582912.0f;
    int   n = __float_as_int(z) - 0x4B400000;
    float f = y - (z - 12582912.0f);
    float p = 1.3333558146e-3f;
    p = fmaf(p, f, 9.6181291076e-3f);
    p = fmaf(p, f, 5.5504108665e-2f);
    p = fmaf(p, f, 2.4022650696e-1f);
    p = fmaf(p, f, 6.9314718056e-1f);
    p = fmaf(p, f, 1.0f);
    return __int_as_float(__float_as_int(p) + (n << 23));
}

// ---------------------------------------------------------------------------
__global__ void detect_mask_kernel(const uint4* __restrict__ m) {
    __shared__ int s_off4, s_gt1;
    if (threadIdx.x == 0) { s_off4 = 0; s_gt1 = 0; }
    __syncthreads();
    int off4 = 0, gt1 = 0;
    for (int i = threadIdx.x; i < 4096; i += blockDim.x) {
        uint4 v = m[i];
        unsigned a = v.x | v.y | v.z | v.w;
        if (a & 0xFFFFFF00u) off4 = 1;
        if (a & 0xFEFEFEFEu) gt1  = 1;
    }
    if (off4) atomicOr(&s_off4, 1);
    if (gt1)  atomicOr(&s_gt1, 1);
    __syncthreads();
    if (threadIdx.x == 0) g_mask_mode = s_gt1 ? 2 : (s_off4 ? 0 : 1);
}

// ---------------------------------------------------------------------------
// Bit-pack the mask: one output word = 32 mask entries. 100MB -> 12.6MB.
// ---------------------------------------------------------------------------
#define B4(t) (((t) | ((t) >> 7) | ((t) >> 14) | ((t) >> 21)) & 0xFu)

__global__ void maskpack_kernel(const unsigned char* __restrict__ m) {
    int w = blockIdx.x * blockDim.x + threadIdx.x;
    if (w >= MWORDS) return;
    int mode = g_mask_mode;
    uint32_t bits = 0;
    if (mode == 0) {
        const uint4* p = (const uint4*)m + w * 2;
        uint4 a = p[0], b = p[1];
        bits  = B4(a.x) | (B4(a.y) << 4) | (B4(a.z) << 8)  | (B4(a.w) << 12)
              | (B4(b.x) << 16) | (B4(b.y) << 20) | (B4(b.z) << 24) | (B4(b.w) << 28);
    } else if (mode == 1) {
        const int4* p = (const int4*)m + w * 8;
        #pragma unroll
        for (int i = 0; i < 8; i++) {
            int4 v = p[i];
            bits |= (uint32_t)((v.x != 0) | ((v.y != 0) << 1) |
                               ((v.z != 0) << 2) | ((v.w != 0) << 3)) << (i * 4);
        }
    } else {
        const float4* p = (const float4*)m + w * 8;
        #pragma unroll
        for (int i = 0; i < 8; i++) {
            float4 v = p[i];
            bits |= (uint32_t)((v.x != 0.f) | ((v.y != 0.f) << 1) |
                               ((v.z != 0.f) << 2) | ((v.w != 0.f) << 3)) << (i * 4);
        }
    }
    g_mbits[w] = bits;
}

// ---------------------------------------------------------------------------
// Pre-split W into bf16 hi/lo k-pairs (done ONCE)
// ---------------------------------------------------------------------------
__global__ void wsplit_kernel(const float* __restrict__ w) {
    int idx = blockIdx.x * blockDim.x + threadIdx.x;   // pair index
    if (idx >= O3C * (C_ / 2)) return;
    float2 v = *(const float2*)&w[idx * 2];
    __nv_bfloat16 h0 = __float2bfloat16(v.x);
    __nv_bfloat16 h1 = __float2bfloat16(v.y);
    g_wh[idx] = ((uint32_t)*(uint16_t*)&h1 << 16) | *(uint16_t*)&h0;
    g_wl[idx] = pack_bf16(v.x - __bfloat162float(h0),
                          v.y - __bfloat162float(h1));
}

// ---------------------------------------------------------------------------
// QKV GEMM, bf16 hi/lo 3-term, m16n8k16, register-prefetched chunks.
// Epilogue rounds outputs to tf32 so attention can copy raw (identity).
// ---------------------------------------------------------------------------
#define WPST 12
#define XPST 136
#define NCHUNK (C_ / 16)

__global__ __launch_bounds__(256, 2) void qkv_gemm_kernel(
    const float* __restrict__ x)
{
    __shared__ uint32_t Whp[128 * WPST], Wlp[128 * WPST];
    __shared__ uint32_t Xhp[8 * XPST],   Xlp[8 * XPST];

    const int b  = blockIdx.z;
    const int o0 = blockIdx.y * 128;
    const int n0 = blockIdx.x * 128;
    const int tid  = threadIdx.x;
    const int wid  = tid >> 5;
    const int lane = tid & 31;
    const int m_base = (wid >> 1) * 32;
    const int n_base = (wid & 1) * 64;
    const int gi = lane >> 2;
    const int ti = lane & 3;

    const float* xb = x + b * C_ * N_;

    const int wo  = tid >> 1;
    const int wk2 = (tid & 1) * 4;
    const int xc2 = tid >> 5;
    const int xn  = (tid & 31) * 4;

    float acc[2][8][4];
    #pragma unroll
    for (int mf = 0; mf < 2; mf++)
        #pragma unroll
        for (int nf = 0; nf < 8; nf++)
            #pragma unroll
            for (int k = 0; k < 4; k++) acc[mf][nf][k] = 0.f;

    const uint32_t* wh_p = &g_wh[(o0 + wo) * (C_ / 2) + wk2];
    const uint32_t* wl_p = &g_wl[(o0 + wo) * (C_ / 2) + wk2];
    const float*    x_p  = &xb[(2 * xc2) * N_ + n0 + xn];
    uint4  whv = *(const uint4*)wh_p;
    uint4  wlv = *(const uint4*)wl_p;
    float4 xr0 = *(const float4*)x_p;
    float4 xr1 = *(const float4*)(x_p + N_);

    for (int ci = 0; ci < NCHUNK; ci++) {
        *(uint4*)&Whp[wo * WPST + wk2] = whv;
        *(uint4*)&Wlp[wo * WPST + wk2] = wlv;
        {
            float a0[4] = {xr0.x, xr0.y, xr0.z, xr0.w};
            float a1[4] = {xr1.x, xr1.y, xr1.z, xr1.w};
            uint32_t ph[4], pl[4];
            #pragma unroll
            for (int j = 0; j < 4; j++) {
                __nv_bfloat16 h0 = __float2bfloat16(a0[j]);
                __nv_bfloat16 h1 = __float2bfloat16(a1[j]);
                ph[j] = ((uint32_t)*(uint16_t*)&h1 << 16) | *(uint16_t*)&h0;
                pl[j] = pack_bf16(a0[j] - __bfloat162float(h0),
                                  a1[j] - __bfloat162float(h1));
            }
            *(uint4*)&Xhp[xc2 * XPST + xn] = make_uint4(ph[0], ph[1], ph[2], ph[3]);
            *(uint4*)&Xlp[xc2 * XPST + xn] = make_uint4(pl[0], pl[1], pl[2], pl[3]);
        }
        __syncthreads();

        if (ci + 1 < NCHUNK) {
            wh_p += 8; wl_p += 8; x_p += 16 * N_;
            whv = *(const uint4*)wh_p;
            wlv = *(const uint4*)wl_p;
            xr0 = *(const float4*)x_p;
            xr1 = *(const float4*)(x_p + N_);
        }

        uint32_t ah[2][4], al[2][4];
        #pragma unroll
        for (int mf = 0; mf < 2; mf++) {
            int r = m_base + mf * 16 + gi;
            ah[mf][0] = Whp[r * WPST + ti];
            ah[mf][1] = Whp[(r + 8) * WPST + ti];
            ah[mf][2] = Whp[r * WPST + ti + 4];
            ah[mf][3] = Whp[(r + 8) * WPST + ti + 4];
            al[mf][0] = Wlp[r * WPST + ti];
            al[mf][1] = Wlp[(r + 8) * WPST + ti];
            al[mf][2] = Wlp[r * WPST + ti + 4];
            al[mf][3] = Wlp[(r + 8) * WPST + ti + 4];
        }
        #pragma unroll
        for (int nf = 0; nf < 8; nf++) {
            int col = n_base + nf * 8 + gi;
            uint32_t bh0 = Xhp[ti * XPST + col];
            uint32_t bh1 = Xhp[(ti + 4) * XPST + col];
            uint32_t bl0 = Xlp[ti * XPST + col];
            uint32_t bl1 = Xlp[(ti + 4) * XPST + col];
            #pragma unroll
            for (int mf = 0; mf < 2; mf++) {
                mma16(acc[mf][nf], ah[mf], bh0, bh1);
                mma16(acc[mf][nf], ah[mf], bl0, bl1);
                mma16(acc[mf][nf], al[mf], bh0, bh1);
            }
        }
        __syncthreads();
    }

    // Epilogue: round to tf32 (rna) so attention reads are conversion-free.
    float* outb = g_qkv + b * O3C * N_;
    #pragma unroll
    for (int mf = 0; mf < 2; mf++) {
        int r = o0 + m_base + mf * 16 + gi;
        #pragma unroll
        for (int nf = 0; nf < 8; nf++) {
            int nc = n0 + n_base + nf * 8 + 2 * ti;
            *(float2*)&outb[r * N_ + nc] = make_float2(
                __uint_as_float(f2tf32(acc[mf][nf][0])),
                __uint_as_float(f2tf32(acc[mf][nf][1])));
            *(float2*)&outb[(r + 8) * N_ + nc] = make_float2(
                __uint_as_float(f2tf32(acc[mf][nf][2])),
                __uint_as_float(f2tf32(acc[mf][nf][3])));
        }
    }
}

// ---------------------------------------------------------------------------
// Fused flash attention, tf32 mma. 128 q rows, 8 warps (16 q each).
// Double-buffered cp.async K/V fills; bit-packed mask prefetched per chunk.
// grid = (8, 6, 16)
// ---------------------------------------------------------------------------
#define AST 68
#define KST 72
#define QP_OFF 0
#define K0_OFF (128 * AST)            // 8704
#define V0_OFF (K0_OFF + 64 * KST)    // 13312
#define K1_OFF (V0_OFF + 64 * AST)    // 17664
#define V1_OFF (K1_OFF + 64 * KST)    // 22272
#define SMEM_WORDS (V1_OFF + 64 * AST) // 26624
#define ATTN_SMEM (SMEM_WORDS * 4)     // 106496 B

__global__ __launch_bounds__(256, 2) void attn_kernel(float* __restrict__ out)
{
    extern __shared__ uint32_t As[];
    uint32_t* QP = As;                       // [128][AST]  Q then P

    const int q0 = blockIdx.x * 128;
    const int h  = blockIdx.y;
    const int b  = blockIdx.z;
    const int tid  = threadIdx.x;
    const int wid  = tid >> 5;
    const int lane = tid & 31;
    const int gi = lane >> 2;
    const int ti = lane & 3;
    const int wq = wid * 16;

    const float sc2 = rsqrtf((float)C_) * 1.4426950408889634f;
    const float NEG = -1e30f;

    const float* qb = g_qkv + (b * O3C + h * D_) * N_;
    const float* kb = qb + C_ * N_;
    const float* vb = qb + 2 * C_ * N_;

    const int mbase = (b * HEADS_ + h) * N_ * N_;

    // cp.async fill of K/V chunk into buffer sel
    auto fill = [&](int sel, int k0) {
        uint32_t* Kb = As + (sel ? K1_OFF : K0_OFF);
        uint32_t* Vb = As + (sel ? V1_OFF : V0_OFF);
        #pragma unroll
        for (int i = 0; i < 4; i++) {
            int e = tid + i * 256;
            int dd = e >> 4, m4 = (e & 15) * 4;
            cpa16(&Kb[dd * KST + m4], &kb[dd * N_ + k0 + m4]);
            cpa16(&Vb[dd * AST + m4], &vb[dd * N_ + k0 + m4]);
        }
        asm volatile("cp.async.commit_group;" ::: "memory");
    };

    // prologue: start chunk 0 fill immediately
    fill(0, 0);

    // ---- Stage Q tile [128 q x 64 d] transposed (already tf32; raw copy) ----
    for (int e = tid; e < 64 * 32; e += 256) {
        int dd = e >> 5, q4 = (e & 31) * 4;
        uint4 v = *(const uint4*)&qb[dd * N_ + q0 + q4];
        QP[(q4 + 0) * AST + dd] = v.x;
        QP[(q4 + 1) * AST + dd] = v.y;
        QP[(q4 + 2) * AST + dd] = v.z;
        QP[(q4 + 3) * AST + dd] = v.w;
    }
    __syncthreads();

    // ---- Cache Q A-fragments in registers ----
    uint32_t qa[8][4];
    #pragma unroll
    for (int ks = 0; ks < 8; ks++) {
        int r = wq + gi, c = ks * 8 + ti;
        qa[ks][0] = QP[r * AST + c];
        qa[ks][1] = QP[(r + 8) * AST + c];
        qa[ks][2] = QP[r * AST + c + 4];
        qa[ks][3] = QP[(r + 8) * AST + c + 4];
    }
    __syncthreads();   // all warps done reading Q before QP reused as P

    float oa[8][4];
    #pragma unroll
    for (int nf = 0; nf < 8; nf++)
        #pragma unroll
        for (int k = 0; k < 4; k++) oa[nf][k] = 0.f;
    float m1 = NEG, m2 = NEG, l1 = 0.f, l2 = 0.f;

    const int r1g = q0 + wq + gi;
    const int mrow = (mbase + r1g * N_) >> 5;   // word index of row r1g

    for (int kc = 0; kc < 16; kc++) {
        const int k0 = kc * 64;
        asm volatile("cp.async.wait_group 0;" ::: "memory");
        __syncthreads();   // buffer[kc&1] ready; all warps done with prev chunk

        // prefetch mask bits for this chunk (retires under the S mma block)
        const int widx = mrow + (k0 >> 5);
        uint2 mwa = *(const uint2*)&g_mbits[widx];          // row r1g
        uint2 mwc = *(const uint2*)&g_mbits[widx + 256];    // row r1g + 8

        // start next chunk's fill into the other buffer
        if (kc + 1 < 16) fill((kc + 1) & 1, k0 + 64);

        const uint32_t* Kc = As + ((kc & 1) ? K1_OFF : K0_OFF);
        const uint32_t* Vc = As + ((kc & 1) ? V1_OFF : V0_OFF);

        // ---- S = Q K^T : warp computes [16 x 64] ----
        float sa[8][4];
        #pragma unroll
        for (int nf = 0; nf < 8; nf++)
            #pragma unroll
            for (int k = 0; k < 4; k++) sa[nf][k] = 0.f;
        #pragma unroll
        for (int ks = 0; ks < 8; ks++) {
            #pragma unroll
            for (int nf = 0; nf < 8; nf++) {
                uint32_t b0 = Kc[(ks * 8 + ti) * KST + nf * 8 + gi];
                uint32_t b1 = Kc[(ks * 8 + ti + 4) * KST + nf * 8 + gi];
                mma8(sa[nf], qa[ks], b0, b1);
            }
        }

        // ---- scale + mask (bits from registers) ----
        #pragma unroll
        for (int nf = 0; nf < 8; nf++) {
            uint32_t wa = (nf < 4) ? mwa.x : mwa.y;
            uint32_t wc = (nf < 4) ? mwc.x : mwc.y;
            int sh = (nf & 3) * 8 + 2 * ti;
            sa[nf][0] = ((wa >> sh) & 1)       ? NEG : sa[nf][0] * sc2;
            sa[nf][1] = ((wa >> (sh + 1)) & 1) ? NEG : sa[nf][1] * sc2;
            sa[nf][2] = ((wc >> sh) & 1)       ? NEG : sa[nf][2] * sc2;
            sa[nf][3] = ((wc >> (sh + 1)) & 1) ? NEG : sa[nf][3] * sc2;
        }

        // ---- online softmax ----
        float mx1 = NEG, mx2 = NEG;
        #pragma unroll
        for (int nf = 0; nf < 8; nf++) {
            mx1 = fmaxf(mx1, fmaxf(sa[nf][0], sa[nf][1]));
            mx2 = fmaxf(mx2, fmaxf(sa[nf][2], sa[nf][3]));
        }
        mx1 = fmaxf(mx1, __shfl_xor_sync(0xffffffffu, mx1, 1));
        mx1 = fmaxf(mx1, __shfl_xor_sync(0xffffffffu, mx1, 2));
        mx2 = fmaxf(mx2, __shfl_xor_sync(0xffffffffu, mx2, 1));
        mx2 = fmaxf(mx2, __shfl_xor_sync(0xffffffffu, mx2, 2));
        float mn1 = fmaxf(m1, mx1), mn2 = fmaxf(m2, mx2);
        float corr1 = fexp2(m1 - mn1), corr2 = fexp2(m2 - mn2);

        float ls1 = 0.f, ls2 = 0.f;
        #pragma unroll
        for (int nf = 0; nf < 8; nf++) {
            float p00 = fexp2(sa[nf][0] - mn1);
            float p01 = fexp2(sa[nf][1] - mn1);
            float p10 = fexp2(sa[nf][2] - mn2);
            float p11 = fexp2(sa[nf][3] - mn2);
            ls1 += p00 + p01;
            ls2 += p10 + p11;
            int col = nf * 8 + 2 * ti;
            QP[(wq + gi) * AST + col]         = f2tf32(p00);
            QP[(wq + gi) * AST + col + 1]     = f2tf32(p01);
            QP[(wq + gi + 8) * AST + col]     = f2tf32(p10);
            QP[(wq + gi + 8) * AST + col + 1] = f2tf32(p11);
        }
        ls1 += __shfl_xor_sync(0xffffffffu, ls1, 1);
        ls1 += __shfl_xor_sync(0xffffffffu, ls1, 2);
        ls2 += __shfl_xor_sync(0xffffffffu, ls2, 1);
        ls2 += __shfl_xor_sync(0xffffffffu, ls2, 2);
        l1 = l1 * corr1 + ls1;
        l2 = l2 * corr2 + ls2;
        m1 = mn1; m2 = mn2;
        #pragma unroll
        for (int nf = 0; nf < 8; nf++) {
            oa[nf][0] *= corr1; oa[nf][1] *= corr1;
            oa[nf][2] *= corr2; oa[nf][3] *= corr2;
        }
        __syncwarp();   // P warp-local

        // ---- O += P V ----
        #pragma unroll
        for (int kf = 0; kf < 8; kf++) {
            uint32_t pa[4];
            int r = wq + gi, c = kf * 8 + ti;
            pa[0] = QP[r * AST + c];
            pa[1] = QP[(r + 8) * AST + c];
            pa[2] = QP[r * AST + c + 4];
            pa[3] = QP[(r + 8) * AST + c + 4];
            #pragma unroll
            for (int nf = 0; nf < 8; nf++) {
                uint32_t b0 = Vc[(nf * 8 + gi) * AST + kf * 8 + ti];
                uint32_t b1 = Vc[(nf * 8 + gi) * AST + kf * 8 + ti + 4];
                mma8(oa[nf], pa, b0, b1);
            }
        }
        // no trailing sync: next iteration's wait+sync covers buffer reuse
    }
    __syncthreads();   // all warps done before Od overlays K0/V0

    // ---- normalize + stage to smem [d][q] for coalesced output ----
    float* Od = (float*)(As + K0_OFF);   // [64][132] staging (overlays K0/V0)
    float il1 = 1.0f / l1, il2 = 1.0f / l2;
    #pragma unroll
    for (int nf = 0; nf < 8; nf++) {
        int d0 = nf * 8 + 2 * ti;
        Od[d0 * 132 + wq + gi]           = oa[nf][0] * il1;
        Od[(d0 + 1) * 132 + wq + gi]     = oa[nf][1] * il1;
        Od[d0 * 132 + wq + gi + 8]       = oa[nf][2] * il2;
        Od[(d0 + 1) * 132 + wq + gi + 8] = oa[nf][3] * il2;
    }
    __syncthreads();

    float* ob = out + (b * C_ + h * D_) * N_;
    for (int e = tid; e < 64 * 32; e += 256) {
        int dd = e >> 5, q4 = (e & 31) * 4;
        *(float4*)&ob[dd * N_ + q0 + q4] = *(const float4*)&Od[dd * 132 + q4];
    }
}

// ---------------------------------------------------------------------------
extern "C" void kernel_launch(void* const* d_in, const int* in_sizes, int n_in,
                              void* d_out, int out_size)
{
    const float* x         = (const float*)d_in[0];
    const float* w_qkv     = (const float*)d_in[1];
    const unsigned char* m = (const unsigned char*)d_in[2];
    float* out             = (float*)d_out;

    cudaFuncSetAttribute(attn_kernel,
                         cudaFuncAttributeMaxDynamicSharedMemorySize, ATTN_SMEM);

    detect_mask_kernel<<<1, 1024>>>((const uint4*)m);
    maskpack_kernel<<<MWORDS / 256, 256>>>(m);
    wsplit_kernel<<<(O3C * (C_ / 2) + 255) / 256, 256>>>(w_qkv);

    dim3 gemm_grid(N_ / 128, O3C / 128, B_);   // (8, 9, 16)
    qkv_gemm_kernel<<<gemm_grid, 256>>>(x);

    dim3 attn_grid(N_ / 128, HEADS_, B_);      // (8, 6, 16)
    attn_kernel<<<attn_grid, 256, ATTN_SMEM>>>(out);
}